// round 2
// baseline (speedup 1.0000x reference)
#include <cuda_runtime.h>

#define NN 200000
#define EE 6400000
#define FF 128
#define HH 16
#define CC 40

// ---------------- scratch (static device globals; no allocation) ----------------
__device__ int   g_cnt[NN];
__device__ int   g_scan[NN];
__device__ int   g_rowptr[NN + 1];
__device__ int   g_cursor[NN];
__device__ int   g_bsum[256];
__device__ int   g_boff[256];
__device__ float g_dis[NN];
__device__ int   g_srcs[EE];
__device__ float g_hA[NN * HH];
__device__ float g_hB[NN * HH];

// ---------------- CSR construction ----------------
__global__ void k_zero() {
    int i = blockIdx.x * 256 + threadIdx.x;
    if (i < NN) g_cnt[i] = 0;
}

__global__ void k_hist(const int* __restrict__ ei) {
    int e = blockIdx.x * 256 + threadIdx.x;
    if (e < EE) atomicAdd(&g_cnt[ei[EE + e]], 1);
}

__global__ void k_dis() {
    int i = blockIdx.x * 256 + threadIdx.x;
    if (i < NN) g_dis[i] = rsqrtf((float)(g_cnt[i] + 1));  // +1 self loop
}

__global__ void k_scan1() {  // 1024 elems per block, inclusive scan
    __shared__ int sh[1024];
    int t = threadIdx.x;
    int i = blockIdx.x * 1024 + t;
    int v = (i < NN) ? g_cnt[i] : 0;
    sh[t] = v;
    for (int off = 1; off < 1024; off <<= 1) {
        __syncthreads();
        int u = (t >= off) ? sh[t - off] : 0;
        __syncthreads();
        sh[t] += u;
    }
    __syncthreads();
    if (i < NN) g_scan[i] = sh[t];
    if (t == 1023) g_bsum[blockIdx.x] = sh[1023];
}

__global__ void k_scan2(int nb) {
    if (threadIdx.x == 0) {
        int run = 0;
        for (int j = 0; j < nb; j++) { g_boff[j] = run; run += g_bsum[j]; }
    }
}

__global__ void k_scan3() {
    int i = blockIdx.x * 256 + threadIdx.x;
    if (i < NN) {
        int ex = g_boff[i >> 10] + g_scan[i] - g_cnt[i];  // exclusive prefix
        g_rowptr[i] = ex;
        g_cursor[i] = ex;
    }
    if (i == 0) g_rowptr[NN] = EE;
}

__global__ void k_scatter(const int* __restrict__ ei) {
    int e = blockIdx.x * 256 + threadIdx.x;
    if (e < EE) {
        int d = ei[EE + e];
        int s = ei[e];
        int p = atomicAdd(&g_cursor[d], 1);
        g_srcs[p] = s;
    }
}

// ---------------- first transform: t0 = x @ w_in  (200000x128 @ 128x16) ----------------
__global__ __launch_bounds__(256) void k_xw(const float* __restrict__ x,
                                            const float* __restrict__ w) {
    __shared__ float xs[16 * 128];
    __shared__ float ws[128 * 16];
    int t = threadIdx.x;
    for (int i = t; i < 2048; i += 256) ws[i] = w[i];
    const float* xb = x + (size_t)blockIdx.x * 2048;
    for (int i = t; i < 2048; i += 256) xs[i] = xb[i];
    __syncthreads();
    int ry = t >> 4, c = t & 15;
    float s = 0.f;
#pragma unroll
    for (int k = 0; k < 128; k++) s = fmaf(xs[ry * 128 + k], ws[k * 16 + c], s);
    g_hA[((size_t)blockIdx.x * 16 + ry) * 16 + c] = s;
}

// ---------------- fused aggregation layers ----------------
// 4 threads per node; each thread owns one float4 chunk of the 16-dim feature.
__device__ __forceinline__ float4 agg_edge(const float4* __restrict__ in,
                                           int node, int sub, float di) {
    float4 acc = __ldg(&in[node * 4 + sub]);  // self loop
    float sw = di * di;
    acc.x *= sw; acc.y *= sw; acc.z *= sw; acc.w *= sw;
    int e = g_rowptr[node], e1 = g_rowptr[node + 1];
    for (; e < e1; ++e) {
        int s = g_srcs[e];
        float w = g_dis[s] * di;
        float4 v = __ldg(&in[s * 4 + sub]);
        acc.x = fmaf(w, v.x, acc.x);
        acc.y = fmaf(w, v.y, acc.y);
        acc.z = fmaf(w, v.z, acc.z);
        acc.w = fmaf(w, v.w, acc.w);
    }
    return acc;
}

// MODE 0: h = relu(agg(in)+preBias); out = h @ Wn (16x16)     [used 8x]
// MODE 1: out = relu(agg(in)+preBias)                          [produces h9]
// MODE 2: o = agg(in) @ w_out + b_out; out = log_softmax(o)    [final, writes d_out]
template <int MODE>
__global__ __launch_bounds__(256) void k_agg(int inA,
                                             const float* __restrict__ preBias,
                                             const float* __restrict__ Wn,
                                             const float* __restrict__ postBias,
                                             float* __restrict__ fout) {
    __shared__ float wsh[640];
    __shared__ float bsh[40];
    __shared__ float hsh[64 * 17];
    int t = threadIdx.x;
    if (MODE == 0) {
        wsh[t] = Wn[t & 255];  // 256 weights, 256 threads
    }
    if (MODE == 2) {
        for (int i = t; i < 640; i += 256) wsh[i] = Wn[i];
        if (t < 40) bsh[t] = postBias[t];
    }
    __syncthreads();

    const float* inF = inA ? g_hA : g_hB;
    float* outF = inA ? g_hB : g_hA;

    int node = blockIdx.x * 64 + (t >> 2);  // grid is exactly N/64 blocks
    int sub = t & 3;
    float di = g_dis[node];
    float4 acc = agg_edge((const float4*)inF, node, sub, di);

    if (MODE != 2) {  // bias + relu
        float4 b4 = __ldg(&((const float4*)preBias)[sub]);
        acc.x = fmaxf(acc.x + b4.x, 0.f);
        acc.y = fmaxf(acc.y + b4.y, 0.f);
        acc.z = fmaxf(acc.z + b4.z, 0.f);
        acc.w = fmaxf(acc.w + b4.w, 0.f);
    }

    if (MODE == 1) {
        ((float4*)outF)[node * 4 + sub] = acc;
        return;
    }

    // share the node's full 16-vector across its 4-lane group
    float* hr = &hsh[(t >> 2) * 17];
    hr[sub * 4 + 0] = acc.x;
    hr[sub * 4 + 1] = acc.y;
    hr[sub * 4 + 2] = acc.z;
    hr[sub * 4 + 3] = acc.w;
    __syncwarp();

    if (MODE == 0) {  // 16x16 transform for the next layer
#pragma unroll
        for (int j = 0; j < 4; j++) {
            int col = sub * 4 + j;
            float o = 0.f;
#pragma unroll
            for (int k = 0; k < 16; k++) o = fmaf(hr[k], wsh[k * 16 + col], o);
            outF[node * 16 + col] = o;
        }
    } else {  // MODE 2: 16x40 output transform + log_softmax
        float o[10];
#pragma unroll
        for (int j = 0; j < 10; j++) {
            int col = sub * 10 + j;
            float s = bsh[col];
#pragma unroll
            for (int k = 0; k < 16; k++) s = fmaf(hr[k], wsh[k * 40 + col], s);
            o[j] = s;
        }
        float m = o[0];
#pragma unroll
        for (int j = 1; j < 10; j++) m = fmaxf(m, o[j]);
        m = fmaxf(m, __shfl_xor_sync(0xffffffffu, m, 1));
        m = fmaxf(m, __shfl_xor_sync(0xffffffffu, m, 2));
        float se = 0.f;
#pragma unroll
        for (int j = 0; j < 10; j++) se += __expf(o[j] - m);
        se += __shfl_xor_sync(0xffffffffu, se, 1);
        se += __shfl_xor_sync(0xffffffffu, se, 2);
        float l = m + __logf(se);
#pragma unroll
        for (int j = 0; j < 10; j++)
            fout[(size_t)node * 40 + sub * 10 + j] = o[j] - l;
    }
}

// ---------------- launch ----------------
extern "C" void kernel_launch(void* const* d_in, const int* in_sizes, int n_in,
                              void* d_out, int out_size) {
    const float* x     = (const float*)d_in[0];
    const float* w_in  = (const float*)d_in[1];
    const float* b_in  = (const float*)d_in[2];
    const float* w_hid = (const float*)d_in[3];
    const float* b_hid = (const float*)d_in[4];
    const float* w_out = (const float*)d_in[5];
    const float* b_out = (const float*)d_in[6];
    const int*   ei    = (const int*)d_in[7];   // JAX x64 disabled -> int32
    float* out = (float*)d_out;

    const int NB_N = (NN + 255) / 256;   // 782
    const int NB_E = EE / 256;           // 25000
    const int NB_S = (NN + 1023) / 1024; // 196
    const int NB_A = NN / 64;            // 3125 (exact)

    // CSR build
    k_zero<<<NB_N, 256>>>();
    k_hist<<<NB_E, 256>>>(ei);
    k_dis<<<NB_N, 256>>>();
    k_scan1<<<NB_S, 1024>>>();
    k_scan2<<<1, 32>>>(NB_S);
    k_scan3<<<NB_N, 256>>>();
    k_scatter<<<NB_E, 256>>>(ei);

    // t0 = x @ w_in  -> g_hA
    k_xw<<<NN / 16, 256>>>(x, w_in);

    // layers 1..8: fused agg + bias + relu + next 16x16 transform (ping-pong)
    k_agg<0><<<NB_A, 256>>>(1, b_in,         w_hid + 0 * 256, nullptr, nullptr);
    k_agg<0><<<NB_A, 256>>>(0, b_hid + 0*16, w_hid + 1 * 256, nullptr, nullptr);
    k_agg<0><<<NB_A, 256>>>(1, b_hid + 1*16, w_hid + 2 * 256, nullptr, nullptr);
    k_agg<0><<<NB_A, 256>>>(0, b_hid + 2*16, w_hid + 3 * 256, nullptr, nullptr);
    k_agg<0><<<NB_A, 256>>>(1, b_hid + 3*16, w_hid + 4 * 256, nullptr, nullptr);
    k_agg<0><<<NB_A, 256>>>(0, b_hid + 4*16, w_hid + 5 * 256, nullptr, nullptr);
    k_agg<0><<<NB_A, 256>>>(1, b_hid + 5*16, w_hid + 6 * 256, nullptr, nullptr);
    k_agg<0><<<NB_A, 256>>>(0, b_hid + 6*16, w_hid + 7 * 256, nullptr, nullptr);
    // layer 9: h9 = relu(agg(t8) + b_hid[7])   (hA -> hB)
    k_agg<1><<<NB_A, 256>>>(1, b_hid + 7*16, nullptr, nullptr, nullptr);
    // layer 10: out = log_softmax(agg16(h9) @ w_out + b_out)   (linearity trick)
    k_agg<2><<<NB_A, 256>>>(0, nullptr, w_out, b_out, out);
}

// round 3
// speedup vs baseline: 1.0241x; 1.0241x over previous
#include <cuda_runtime.h>

#define NN 200000
#define EE 6400000
#define FF 128
#define HH 16
#define CC 40
#define NBIN 512

// ---------------- scratch (static device globals; no allocation) ----------------
__device__ int       g_cnt[NN];
__device__ int       g_scan[NN];
__device__ int       g_rowptr[NN + 1];
__device__ int       g_cursor[NN];
__device__ int       g_bsum[256];
__device__ int       g_boff[256];
__device__ float     g_dis[NN];
__device__ long long g_pk[EE];        // packed {src, weight}
__device__ int       g_order[NN];     // degree-sorted node order
__device__ int       g_dbin[NBIN];
__device__ int       g_doff[NBIN];
__device__ int       g_dcur[NBIN];
__device__ float     g_hA[NN * HH];
__device__ float     g_hB[NN * HH];

// ---------------- CSR construction ----------------
__global__ void k_zero() {
    int i = blockIdx.x * 256 + threadIdx.x;
    if (i < NN) g_cnt[i] = 0;
}

__global__ void k_hist(const int* __restrict__ ei) {
    int e = blockIdx.x * 256 + threadIdx.x;
    if (e < EE) atomicAdd(&g_cnt[ei[EE + e]], 1);
}

__global__ void k_dis() {
    int i = blockIdx.x * 256 + threadIdx.x;
    if (i < NN) g_dis[i] = rsqrtf((float)(g_cnt[i] + 1));  // +1 self loop
}

__global__ void k_scan1() {  // 1024 elems per block, inclusive scan
    __shared__ int sh[1024];
    int t = threadIdx.x;
    int i = blockIdx.x * 1024 + t;
    int v = (i < NN) ? g_cnt[i] : 0;
    sh[t] = v;
    for (int off = 1; off < 1024; off <<= 1) {
        __syncthreads();
        int u = (t >= off) ? sh[t - off] : 0;
        __syncthreads();
        sh[t] += u;
    }
    __syncthreads();
    if (i < NN) g_scan[i] = sh[t];
    if (t == 1023) g_bsum[blockIdx.x] = sh[1023];
}

__global__ void k_scan2(int nb) {
    if (threadIdx.x == 0) {
        int run = 0;
        for (int j = 0; j < nb; j++) { g_boff[j] = run; run += g_bsum[j]; }
    }
}

__global__ void k_scan3() {
    int i = blockIdx.x * 256 + threadIdx.x;
    if (i < NN) {
        int ex = g_boff[i >> 10] + g_scan[i] - g_cnt[i];  // exclusive prefix
        g_rowptr[i] = ex;
        g_cursor[i] = ex;
    }
    if (i == 0) g_rowptr[NN] = EE;
}

// scatter edges into CSR, packing src index + precomputed norm weight (8B)
__global__ void k_scatter(const int* __restrict__ ei) {
    int e = blockIdx.x * 256 + threadIdx.x;
    if (e < EE) {
        int s = ei[e];
        int d = ei[EE + e];
        int p = atomicAdd(&g_cursor[d], 1);
        float w = g_dis[s] * g_dis[d];
        g_pk[p] = ((long long)__float_as_int(w) << 32) | (unsigned int)s;
    }
}

// ---------------- degree counting sort (for warp-uniform edge loops) ----------
__global__ void k_bz() {
    int t = threadIdx.x;
    g_dbin[t] = 0;
    g_dcur[t] = 0;
}

__global__ void k_dhist() {
    int i = blockIdx.x * 256 + threadIdx.x;
    if (i < NN) {
        int d = g_cnt[i]; if (d > NBIN - 1) d = NBIN - 1;
        atomicAdd(&g_dbin[d], 1);
    }
}

__global__ void k_dscan() {  // single block, 512 threads, exclusive scan
    __shared__ int sh[NBIN];
    int t = threadIdx.x;
    sh[t] = g_dbin[t];
    for (int off = 1; off < NBIN; off <<= 1) {
        __syncthreads();
        int u = (t >= off) ? sh[t - off] : 0;
        __syncthreads();
        sh[t] += u;
    }
    __syncthreads();
    g_doff[t] = sh[t] - g_dbin[t];
}

__global__ void k_dplace() {
    int i = blockIdx.x * 256 + threadIdx.x;
    if (i < NN) {
        int d = g_cnt[i]; if (d > NBIN - 1) d = NBIN - 1;
        int p = g_doff[d] + atomicAdd(&g_dcur[d], 1);
        g_order[p] = i;
    }
}

// ---------------- first transform: t0 = x @ w_in  (200000x128 @ 128x16) ----------------
__global__ __launch_bounds__(256) void k_xw(const float* __restrict__ x,
                                            const float* __restrict__ w) {
    __shared__ float xs[16 * 128];
    __shared__ float ws[128 * 16];
    int t = threadIdx.x;
    for (int i = t; i < 2048; i += 256) ws[i] = w[i];
    const float* xb = x + (size_t)blockIdx.x * 2048;
    for (int i = t; i < 2048; i += 256) xs[i] = xb[i];
    __syncthreads();
    int ry = t >> 4, c = t & 15;
    float s = 0.f;
#pragma unroll
    for (int k = 0; k < 128; k++) s = fmaf(xs[ry * 128 + k], ws[k * 16 + c], s);
    g_hA[((size_t)blockIdx.x * 16 + ry) * 16 + c] = s;
}

// ---------------- fused aggregation layers ----------------
// 4 threads per node; each thread owns one float4 chunk of the 16-dim feature.
__device__ __forceinline__ float4 agg_edge(const float4* __restrict__ in,
                                           int node, int sub, float di) {
    float4 acc = __ldg(&in[node * 4 + sub]);  // self loop
    float sw = di * di;
    acc.x *= sw; acc.y *= sw; acc.z *= sw; acc.w *= sw;
    int e = g_rowptr[node], e1 = g_rowptr[node + 1];
#pragma unroll 4
    for (; e < e1; ++e) {
        long long pk = __ldg(&g_pk[e]);
        int s = (int)(unsigned int)pk;
        float w = __int_as_float((int)(pk >> 32));
        float4 v = __ldg(&in[s * 4 + sub]);
        acc.x = fmaf(w, v.x, acc.x);
        acc.y = fmaf(w, v.y, acc.y);
        acc.z = fmaf(w, v.z, acc.z);
        acc.w = fmaf(w, v.w, acc.w);
    }
    return acc;
}

// MODE 0: h = relu(agg(in)+preBias); out = h @ Wn (16x16)     [used 8x]
// MODE 1: out = relu(agg(in)+preBias)                          [produces h9]
// MODE 2: o = agg(in) @ w_out + b_out; out = log_softmax(o)    [final, writes d_out]
template <int MODE>
__global__ __launch_bounds__(256) void k_agg(int inA,
                                             const float* __restrict__ preBias,
                                             const float* __restrict__ Wn,
                                             const float* __restrict__ postBias,
                                             float* __restrict__ fout) {
    __shared__ float wsh[640];
    __shared__ float bsh[40];
    __shared__ float hsh[64 * 17];
    int t = threadIdx.x;
    if (MODE == 0) {
        wsh[t] = Wn[t & 255];  // 256 weights, 256 threads
    }
    if (MODE == 2) {
        for (int i = t; i < 640; i += 256) wsh[i] = Wn[i];
        if (t < 40) bsh[t] = postBias[t];
    }
    __syncthreads();

    const float* inF = inA ? g_hA : g_hB;
    float* outF = inA ? g_hB : g_hA;

    int node = g_order[blockIdx.x * 64 + (t >> 2)];  // degree-sorted order
    int sub = t & 3;
    float di = g_dis[node];
    float4 acc = agg_edge((const float4*)inF, node, sub, di);

    if (MODE != 2) {  // bias + relu
        float4 b4 = __ldg(&((const float4*)preBias)[sub]);
        acc.x = fmaxf(acc.x + b4.x, 0.f);
        acc.y = fmaxf(acc.y + b4.y, 0.f);
        acc.z = fmaxf(acc.z + b4.z, 0.f);
        acc.w = fmaxf(acc.w + b4.w, 0.f);
    }

    if (MODE == 1) {
        ((float4*)outF)[node * 4 + sub] = acc;
        return;
    }

    // share the node's full 16-vector across its 4-lane group
    float* hr = &hsh[(t >> 2) * 17];
    hr[sub * 4 + 0] = acc.x;
    hr[sub * 4 + 1] = acc.y;
    hr[sub * 4 + 2] = acc.z;
    hr[sub * 4 + 3] = acc.w;
    __syncwarp();

    if (MODE == 0) {  // 16x16 transform for the next layer
        float o[4];
#pragma unroll
        for (int j = 0; j < 4; j++) {
            int col = sub * 4 + j;
            float s = 0.f;
#pragma unroll
            for (int k = 0; k < 16; k++) s = fmaf(hr[k], wsh[k * 16 + col], s);
            o[j] = s;
        }
        ((float4*)outF)[node * 4 + sub] = make_float4(o[0], o[1], o[2], o[3]);
    } else {  // MODE 2: 16x40 output transform + log_softmax
        float o[10];
#pragma unroll
        for (int j = 0; j < 10; j++) {
            int col = sub * 10 + j;
            float s = bsh[col];
#pragma unroll
            for (int k = 0; k < 16; k++) s = fmaf(hr[k], wsh[k * 40 + col], s);
            o[j] = s;
        }
        float m = o[0];
#pragma unroll
        for (int j = 1; j < 10; j++) m = fmaxf(m, o[j]);
        m = fmaxf(m, __shfl_xor_sync(0xffffffffu, m, 1));
        m = fmaxf(m, __shfl_xor_sync(0xffffffffu, m, 2));
        float se = 0.f;
#pragma unroll
        for (int j = 0; j < 10; j++) se += __expf(o[j] - m);
        se += __shfl_xor_sync(0xffffffffu, se, 1);
        se += __shfl_xor_sync(0xffffffffu, se, 2);
        float l = m + __logf(se);
#pragma unroll
        for (int j = 0; j < 10; j++)
            fout[(size_t)node * 40 + sub * 10 + j] = o[j] - l;
    }
}

// ---------------- launch ----------------
extern "C" void kernel_launch(void* const* d_in, const int* in_sizes, int n_in,
                              void* d_out, int out_size) {
    const float* x     = (const float*)d_in[0];
    const float* w_in  = (const float*)d_in[1];
    const float* b_in  = (const float*)d_in[2];
    const float* w_hid = (const float*)d_in[3];
    const float* b_hid = (const float*)d_in[4];
    const float* w_out = (const float*)d_in[5];
    const float* b_out = (const float*)d_in[6];
    const int*   ei    = (const int*)d_in[7];   // JAX x64 disabled -> int32
    float* out = (float*)d_out;

    const int NB_N = (NN + 255) / 256;   // 782
    const int NB_E = EE / 256;           // 25000
    const int NB_S = (NN + 1023) / 1024; // 196
    const int NB_A = NN / 64;            // 3125 (exact)

    // CSR build
    k_zero<<<NB_N, 256>>>();
    k_hist<<<NB_E, 256>>>(ei);
    k_dis<<<NB_N, 256>>>();
    k_scan1<<<NB_S, 1024>>>();
    k_scan2<<<1, 32>>>(NB_S);
    k_scan3<<<NB_N, 256>>>();
    k_scatter<<<NB_E, 256>>>(ei);

    // degree counting sort
    k_bz<<<1, NBIN>>>();
    k_dhist<<<NB_N, 256>>>();
    k_dscan<<<1, NBIN>>>();
    k_dplace<<<NB_N, 256>>>();

    // t0 = x @ w_in  -> g_hA
    k_xw<<<NN / 16, 256>>>(x, w_in);

    // layers 1..8: fused agg + bias + relu + next 16x16 transform (ping-pong)
    k_agg<0><<<NB_A, 256>>>(1, b_in,         w_hid + 0 * 256, nullptr, nullptr);
    k_agg<0><<<NB_A, 256>>>(0, b_hid + 0*16, w_hid + 1 * 256, nullptr, nullptr);
    k_agg<0><<<NB_A, 256>>>(1, b_hid + 1*16, w_hid + 2 * 256, nullptr, nullptr);
    k_agg<0><<<NB_A, 256>>>(0, b_hid + 2*16, w_hid + 3 * 256, nullptr, nullptr);
    k_agg<0><<<NB_A, 256>>>(1, b_hid + 3*16, w_hid + 4 * 256, nullptr, nullptr);
    k_agg<0><<<NB_A, 256>>>(0, b_hid + 4*16, w_hid + 5 * 256, nullptr, nullptr);
    k_agg<0><<<NB_A, 256>>>(1, b_hid + 5*16, w_hid + 6 * 256, nullptr, nullptr);
    k_agg<0><<<NB_A, 256>>>(0, b_hid + 6*16, w_hid + 7 * 256, nullptr, nullptr);
    // layer 9: h9 = relu(agg(t8) + b_hid[7])   (hA -> hB)
    k_agg<1><<<NB_A, 256>>>(1, b_hid + 7*16, nullptr, nullptr, nullptr);
    // layer 10: out = log_softmax(agg16(h9) @ w_out + b_out)   (linearity trick)
    k_agg<2><<<NB_A, 256>>>(0, nullptr, w_out, b_out, out);
}

// round 4
// speedup vs baseline: 1.0768x; 1.0515x over previous
#include <cuda_runtime.h>
#include <cuda_fp16.h>

#define NN 200000
#define EE 6400000
#define FF 128
#define HH 16
#define CC 40
#define NBIN 512

// ---------------- scratch (static device globals; no allocation) ----------------
__device__ int       g_cnt[NN];
__device__ int       g_scan[NN];
__device__ int       g_rowptr[NN + 1];
__device__ int       g_cursor[NN];
__device__ int       g_bsum[256];
__device__ int       g_boff[256];
__device__ float     g_dis[NN];
__device__ long long g_pk[EE];        // packed {weight(f32) , src(i32)}
__device__ int       g_order[NN];     // degree-sorted node order
__device__ int       g_dbin[NBIN];
__device__ int       g_doff[NBIN];
__device__ int       g_dcur[NBIN];
// features stored fp16: 16 dims * 2B = 32B per node (1 sector per gather)
__device__ __half    g_hA[NN * HH];
__device__ __half    g_hB[NN * HH];

// ---------------- CSR construction ----------------
__global__ void k_zero() {
    int i = blockIdx.x * 256 + threadIdx.x;
    if (i < NN) g_cnt[i] = 0;
    if (i < NBIN) { g_dbin[i] = 0; g_dcur[i] = 0; }
}

__global__ void k_hist(const int* __restrict__ ei) {
    int e = blockIdx.x * 256 + threadIdx.x;
    if (e < EE) atomicAdd(&g_cnt[ei[EE + e]], 1);
}

__global__ void k_dis() {
    int i = blockIdx.x * 256 + threadIdx.x;
    if (i < NN) g_dis[i] = rsqrtf((float)(g_cnt[i] + 1));  // +1 self loop
}

__global__ void k_scan1() {  // 1024 elems per block, inclusive scan
    __shared__ int sh[1024];
    int t = threadIdx.x;
    int i = blockIdx.x * 1024 + t;
    int v = (i < NN) ? g_cnt[i] : 0;
    sh[t] = v;
    for (int off = 1; off < 1024; off <<= 1) {
        __syncthreads();
        int u = (t >= off) ? sh[t - off] : 0;
        __syncthreads();
        sh[t] += u;
    }
    __syncthreads();
    if (i < NN) g_scan[i] = sh[t];
    if (t == 1023) g_bsum[blockIdx.x] = sh[1023];
}

__global__ void k_scan2(int nb) {
    if (threadIdx.x == 0) {
        int run = 0;
        for (int j = 0; j < nb; j++) { g_boff[j] = run; run += g_bsum[j]; }
    }
}

__global__ void k_scan3() {
    int i = blockIdx.x * 256 + threadIdx.x;
    if (i < NN) {
        int ex = g_boff[i >> 10] + g_scan[i] - g_cnt[i];  // exclusive prefix
        g_rowptr[i] = ex;
        g_cursor[i] = ex;
    }
    if (i == 0) g_rowptr[NN] = EE;
}

// scatter edges into CSR, packing src index + precomputed norm weight (8B)
__global__ void k_scatter(const int* __restrict__ ei) {
    int e = blockIdx.x * 256 + threadIdx.x;
    if (e < EE) {
        int s = ei[e];
        int d = ei[EE + e];
        int p = atomicAdd(&g_cursor[d], 1);
        float w = g_dis[s] * g_dis[d];
        g_pk[p] = ((long long)__float_as_int(w) << 32) | (unsigned int)s;
    }
}

// ---------------- degree counting sort (for warp-uniform edge loops) ----------
__global__ void k_dhist() {
    int i = blockIdx.x * 256 + threadIdx.x;
    if (i < NN) {
        int d = g_cnt[i]; if (d > NBIN - 1) d = NBIN - 1;
        atomicAdd(&g_dbin[d], 1);
    }
}

__global__ void k_dscan() {  // single block, 512 threads, exclusive scan
    __shared__ int sh[NBIN];
    int t = threadIdx.x;
    sh[t] = g_dbin[t];
    for (int off = 1; off < NBIN; off <<= 1) {
        __syncthreads();
        int u = (t >= off) ? sh[t - off] : 0;
        __syncthreads();
        sh[t] += u;
    }
    __syncthreads();
    g_doff[t] = sh[t] - g_dbin[t];
}

__global__ void k_dplace() {
    int i = blockIdx.x * 256 + threadIdx.x;
    if (i < NN) {
        int d = g_cnt[i]; if (d > NBIN - 1) d = NBIN - 1;
        int p = g_doff[d] + atomicAdd(&g_dcur[d], 1);
        g_order[p] = i;
    }
}

// ---------------- first transform: t0 = x @ w_in  (200000x128 @ 128x16) ----------------
__global__ __launch_bounds__(256) void k_xw(const float* __restrict__ x,
                                            const float* __restrict__ w) {
    __shared__ float xs[16 * 128];
    __shared__ float ws[128 * 16];
    int t = threadIdx.x;
    for (int i = t; i < 2048; i += 256) ws[i] = w[i];
    const float* xb = x + (size_t)blockIdx.x * 2048;
    for (int i = t; i < 2048; i += 256) xs[i] = xb[i];
    __syncthreads();
    int ry = t >> 4, c = t & 15;
    float s = 0.f;
#pragma unroll
    for (int k = 0; k < 128; k++) s = fmaf(xs[ry * 128 + k], ws[k * 16 + c], s);
    g_hA[((size_t)blockIdx.x * 16 + ry) * 16 + c] = __float2half_rn(s);
}

// ---------------- fused aggregation layers ----------------
// 4 threads per node; each thread owns 4 dims (one 8B fp16x4 chunk).
__device__ __forceinline__ float4 h4_to_f4(uint2 hv) {
    float2 lo = __half22float2(*(__half2*)&hv.x);
    float2 hi = __half22float2(*(__half2*)&hv.y);
    return make_float4(lo.x, lo.y, hi.x, hi.y);
}

__device__ __forceinline__ float4 agg_edge(const uint2* __restrict__ in,
                                           int node, int sub, float di) {
    float4 acc = h4_to_f4(__ldg(&in[node * 4 + sub]));  // self loop
    float sw = di * di;
    acc.x *= sw; acc.y *= sw; acc.z *= sw; acc.w *= sw;
    int e = g_rowptr[node], e1 = g_rowptr[node + 1];
#pragma unroll 4
    for (; e < e1; ++e) {
        long long pk = __ldg(&g_pk[e]);
        int s = (int)(unsigned int)pk;
        float w = __int_as_float((int)(pk >> 32));
        float4 v = h4_to_f4(__ldg(&in[s * 4 + sub]));
        acc.x = fmaf(w, v.x, acc.x);
        acc.y = fmaf(w, v.y, acc.y);
        acc.z = fmaf(w, v.z, acc.z);
        acc.w = fmaf(w, v.w, acc.w);
    }
    return acc;
}

__device__ __forceinline__ uint2 f4_to_h4(float4 v) {
    __half2 lo = __floats2half2_rn(v.x, v.y);
    __half2 hi = __floats2half2_rn(v.z, v.w);
    uint2 r; r.x = *(unsigned int*)&lo; r.y = *(unsigned int*)&hi;
    return r;
}

// MODE 0: h = relu(agg(in)+preBias); out = h @ Wn (16x16)     [used 8x]
// MODE 1: out = relu(agg(in)+preBias)                          [produces h9]
// MODE 2: o = agg(in) @ w_out + b_out; out = log_softmax(o)    [final, writes d_out]
template <int MODE>
__global__ __launch_bounds__(256) void k_agg(int inA,
                                             const float* __restrict__ preBias,
                                             const float* __restrict__ Wn,
                                             const float* __restrict__ postBias,
                                             float* __restrict__ fout) {
    __shared__ float wsh[640];
    __shared__ float bsh[40];
    __shared__ float hsh[64 * 17];
    int t = threadIdx.x;
    if (MODE == 0) {
        wsh[t] = Wn[t & 255];  // 256 weights, 256 threads
    }
    if (MODE == 2) {
        for (int i = t; i < 640; i += 256) wsh[i] = Wn[i];
        if (t < 40) bsh[t] = postBias[t];
    }
    __syncthreads();

    const __half* inF = inA ? g_hA : g_hB;
    __half* outF = inA ? g_hB : g_hA;

    int node = g_order[blockIdx.x * 64 + (t >> 2)];  // degree-sorted order
    int sub = t & 3;
    float di = g_dis[node];
    float4 acc = agg_edge((const uint2*)inF, node, sub, di);

    if (MODE != 2) {  // bias + relu
        float4 b4 = __ldg(&((const float4*)preBias)[sub]);
        acc.x = fmaxf(acc.x + b4.x, 0.f);
        acc.y = fmaxf(acc.y + b4.y, 0.f);
        acc.z = fmaxf(acc.z + b4.z, 0.f);
        acc.w = fmaxf(acc.w + b4.w, 0.f);
    }

    if (MODE == 1) {
        ((uint2*)outF)[node * 4 + sub] = f4_to_h4(acc);
        return;
    }

    // share the node's full 16-vector across its 4-lane group
    float* hr = &hsh[(t >> 2) * 17];
    hr[sub * 4 + 0] = acc.x;
    hr[sub * 4 + 1] = acc.y;
    hr[sub * 4 + 2] = acc.z;
    hr[sub * 4 + 3] = acc.w;
    __syncwarp();

    if (MODE == 0) {  // 16x16 transform for the next layer
        float o[4];
#pragma unroll
        for (int j = 0; j < 4; j++) {
            int col = sub * 4 + j;
            float s = 0.f;
#pragma unroll
            for (int k = 0; k < 16; k++) s = fmaf(hr[k], wsh[k * 16 + col], s);
            o[j] = s;
        }
        ((uint2*)outF)[node * 4 + sub] = f4_to_h4(make_float4(o[0], o[1], o[2], o[3]));
    } else {  // MODE 2: 16x40 output transform + log_softmax
        float o[10];
#pragma unroll
        for (int j = 0; j < 10; j++) {
            int col = sub * 10 + j;
            float s = bsh[col];
#pragma unroll
            for (int k = 0; k < 16; k++) s = fmaf(hr[k], wsh[k * 40 + col], s);
            o[j] = s;
        }
        float m = o[0];
#pragma unroll
        for (int j = 1; j < 10; j++) m = fmaxf(m, o[j]);
        m = fmaxf(m, __shfl_xor_sync(0xffffffffu, m, 1));
        m = fmaxf(m, __shfl_xor_sync(0xffffffffu, m, 2));
        float se = 0.f;
#pragma unroll
        for (int j = 0; j < 10; j++) se += __expf(o[j] - m);
        se += __shfl_xor_sync(0xffffffffu, se, 1);
        se += __shfl_xor_sync(0xffffffffu, se, 2);
        float l = m + __logf(se);
#pragma unroll
        for (int j = 0; j < 10; j++)
            fout[(size_t)node * 40 + sub * 10 + j] = o[j] - l;
    }
}

// ---------------- launch ----------------
extern "C" void kernel_launch(void* const* d_in, const int* in_sizes, int n_in,
                              void* d_out, int out_size) {
    const float* x     = (const float*)d_in[0];
    const float* w_in  = (const float*)d_in[1];
    const float* b_in  = (const float*)d_in[2];
    const float* w_hid = (const float*)d_in[3];
    const float* b_hid = (const float*)d_in[4];
    const float* w_out = (const float*)d_in[5];
    const float* b_out = (const float*)d_in[6];
    const int*   ei    = (const int*)d_in[7];   // JAX x64 disabled -> int32
    float* out = (float*)d_out;

    const int NB_N = (NN + 255) / 256;   // 782
    const int NB_E = EE / 256;           // 25000
    const int NB_S = (NN + 1023) / 1024; // 196
    const int NB_A = NN / 64;            // 3125 (exact)

    // CSR build
    k_zero<<<NB_N, 256>>>();
    k_hist<<<NB_E, 256>>>(ei);
    k_dis<<<NB_N, 256>>>();
    k_scan1<<<NB_S, 1024>>>();
    k_scan2<<<1, 32>>>(NB_S);
    k_scan3<<<NB_N, 256>>>();
    k_scatter<<<NB_E, 256>>>(ei);

    // degree counting sort
    k_dhist<<<NB_N, 256>>>();
    k_dscan<<<1, NBIN>>>();
    k_dplace<<<NB_N, 256>>>();

    // t0 = x @ w_in  -> g_hA
    k_xw<<<NN / 16, 256>>>(x, w_in);

    // layers 1..8: fused agg + bias + relu + next 16x16 transform (ping-pong)
    k_agg<0><<<NB_A, 256>>>(1, b_in,         w_hid + 0 * 256, nullptr, nullptr);
    k_agg<0><<<NB_A, 256>>>(0, b_hid + 0*16, w_hid + 1 * 256, nullptr, nullptr);
    k_agg<0><<<NB_A, 256>>>(1, b_hid + 1*16, w_hid + 2 * 256, nullptr, nullptr);
    k_agg<0><<<NB_A, 256>>>(0, b_hid + 2*16, w_hid + 3 * 256, nullptr, nullptr);
    k_agg<0><<<NB_A, 256>>>(1, b_hid + 3*16, w_hid + 4 * 256, nullptr, nullptr);
    k_agg<0><<<NB_A, 256>>>(0, b_hid + 4*16, w_hid + 5 * 256, nullptr, nullptr);
    k_agg<0><<<NB_A, 256>>>(1, b_hid + 5*16, w_hid + 6 * 256, nullptr, nullptr);
    k_agg<0><<<NB_A, 256>>>(0, b_hid + 6*16, w_hid + 7 * 256, nullptr, nullptr);
    // layer 9: h9 = relu(agg(t8) + b_hid[7])   (hA -> hB)
    k_agg<1><<<NB_A, 256>>>(1, b_hid + 7*16, nullptr, nullptr, nullptr);
    // layer 10: out = log_softmax(agg16(h9) @ w_out + b_out)   (linearity trick)
    k_agg<2><<<NB_A, 256>>>(0, nullptr, w_out, b_out, out);
}

// round 5
// speedup vs baseline: 1.1938x; 1.1086x over previous
#include <cuda_runtime.h>
#include <cuda_fp16.h>

#define NN 200000
#define EE 6400000
#define FF 128
#define HH 16
#define CC 40
#define NBIN 512

// ---------------- scratch (static device globals; no allocation) ----------------
__device__ int       g_cnt[NN];
__device__ int       g_scan[NN];
__device__ int       g_rowptr[NN + 1];
__device__ int       g_cursor[NN];
__device__ int       g_bsum[256];
__device__ int       g_boff[256];
__device__ float     g_dis[NN];
__device__ int       g_srcs[EE];      // src index only (weights folded into features)
__device__ int       g_order[NN];     // degree-sorted node order
__device__ int       g_dbin[NBIN];
__device__ int       g_doff[NBIN];
__device__ int       g_dcur[NBIN];
// features stored fp16 PRE-SCALED by dis[node]: 16 dims * 2B = 32B per node
__device__ __half    g_hA[NN * HH];
__device__ __half    g_hB[NN * HH];

// ---------------- CSR construction ----------------
__global__ void k_zero() {
    int i = blockIdx.x * 256 + threadIdx.x;
    if (i < NN) g_cnt[i] = 0;
    if (i < NBIN) { g_dbin[i] = 0; g_dcur[i] = 0; }
}

__global__ void k_hist(const int* __restrict__ ei) {
    int e = blockIdx.x * 256 + threadIdx.x;
    if (e < EE) atomicAdd(&g_cnt[ei[EE + e]], 1);
}

__global__ void k_scan1() {  // 1024 elems per block, inclusive scan
    __shared__ int sh[1024];
    int t = threadIdx.x;
    int i = blockIdx.x * 1024 + t;
    int v = (i < NN) ? g_cnt[i] : 0;
    sh[t] = v;
    for (int off = 1; off < 1024; off <<= 1) {
        __syncthreads();
        int u = (t >= off) ? sh[t - off] : 0;
        __syncthreads();
        sh[t] += u;
    }
    __syncthreads();
    if (i < NN) g_scan[i] = sh[t];
    if (t == 1023) g_bsum[blockIdx.x] = sh[1023];
}

__global__ void k_scan2(int nb) {
    if (threadIdx.x == 0) {
        int run = 0;
        for (int j = 0; j < nb; j++) { g_boff[j] = run; run += g_bsum[j]; }
    }
}

__global__ void k_scan3() {  // rowptr/cursor + dis (fused)
    int i = blockIdx.x * 256 + threadIdx.x;
    if (i < NN) {
        int ex = g_boff[i >> 10] + g_scan[i] - g_cnt[i];  // exclusive prefix
        g_rowptr[i] = ex;
        g_cursor[i] = ex;
        g_dis[i] = rsqrtf((float)(g_cnt[i] + 1));  // +1 self loop
    }
    if (i == 0) g_rowptr[NN] = EE;
}

// scatter edges into CSR (src index only)
__global__ void k_scatter(const int* __restrict__ ei) {
    int e = blockIdx.x * 256 + threadIdx.x;
    if (e < EE) {
        int s = ei[e];
        int d = ei[EE + e];
        int p = atomicAdd(&g_cursor[d], 1);
        g_srcs[p] = s;
    }
}

// ---------------- degree counting sort (for warp-uniform edge loops) ----------
__global__ void k_dhist() {
    int i = blockIdx.x * 256 + threadIdx.x;
    if (i < NN) {
        int d = g_cnt[i]; if (d > NBIN - 1) d = NBIN - 1;
        atomicAdd(&g_dbin[d], 1);
    }
}

__global__ void k_dscan() {  // single block, 512 threads, exclusive scan
    __shared__ int sh[NBIN];
    int t = threadIdx.x;
    sh[t] = g_dbin[t];
    for (int off = 1; off < NBIN; off <<= 1) {
        __syncthreads();
        int u = (t >= off) ? sh[t - off] : 0;
        __syncthreads();
        sh[t] += u;
    }
    __syncthreads();
    g_doff[t] = sh[t] - g_dbin[t];
}

__global__ void k_dplace() {
    int i = blockIdx.x * 256 + threadIdx.x;
    if (i < NN) {
        int d = g_cnt[i]; if (d > NBIN - 1) d = NBIN - 1;
        int p = g_doff[d] + atomicAdd(&g_dcur[d], 1);
        g_order[p] = i;
    }
}

// -------- first transform: store dis * (x @ w_in)  (200000x128 @ 128x16) --------
__global__ __launch_bounds__(256) void k_xw(const float* __restrict__ x,
                                            const float* __restrict__ w) {
    __shared__ float xs[16 * 128];
    __shared__ float ws[128 * 16];
    int t = threadIdx.x;
    for (int i = t; i < 2048; i += 256) ws[i] = w[i];
    const float* xb = x + (size_t)blockIdx.x * 2048;
    for (int i = t; i < 2048; i += 256) xs[i] = xb[i];
    __syncthreads();
    int ry = t >> 4, c = t & 15;
    float s = 0.f;
#pragma unroll
    for (int k = 0; k < 128; k++) s = fmaf(xs[ry * 128 + k], ws[k * 16 + c], s);
    int node = blockIdx.x * 16 + ry;
    g_hA[(size_t)node * 16 + c] = __float2half_rn(s * g_dis[node]);
}

// ---------------- fused aggregation layers ----------------
// 4 threads per node; each thread owns 4 dims (one 8B fp16x4 chunk).
// Input features are pre-scaled: in[s] = dis[s]*h[s], so aggregation is an
// UNWEIGHTED sum; dis[d] is applied once in the epilogue.
__device__ __forceinline__ float4 h4_to_f4(uint2 hv) {
    float2 lo = __half22float2(*(__half2*)&hv.x);
    float2 hi = __half22float2(*(__half2*)&hv.y);
    return make_float4(lo.x, lo.y, hi.x, hi.y);
}

__device__ __forceinline__ uint2 f4_to_h4(float4 v) {
    __half2 lo = __floats2half2_rn(v.x, v.y);
    __half2 hi = __floats2half2_rn(v.z, v.w);
    uint2 r; r.x = *(unsigned int*)&lo; r.y = *(unsigned int*)&hi;
    return r;
}

__device__ __forceinline__ float4 agg_edge(const uint2* __restrict__ in,
                                           int node, int sub) {
    float4 acc = h4_to_f4(__ldg(&in[node * 4 + sub]));  // self loop term
    int e = g_rowptr[node], e1 = g_rowptr[node + 1];
#pragma unroll 8
    for (; e < e1; ++e) {
        int s = __ldg(&g_srcs[e]);
        float4 v = h4_to_f4(__ldg(&in[s * 4 + sub]));
        acc.x += v.x; acc.y += v.y; acc.z += v.z; acc.w += v.w;
    }
    return acc;
}

// MODE 0: h = relu(dis*agg+b); store dis*(h @ Wn)               [used 8x]
// MODE 1: store dis*relu(dis*agg+b)                              [produces h9-hat]
// MODE 2: o = (dis*agg) @ w_out + b_out; out = log_softmax(o)    [final]
template <int MODE>
__global__ __launch_bounds__(256) void k_agg(int inA,
                                             const float* __restrict__ preBias,
                                             const float* __restrict__ Wn,
                                             const float* __restrict__ postBias,
                                             float* __restrict__ fout) {
    __shared__ float wsh[640];
    __shared__ float bsh[40];
    __shared__ float hsh[64 * 17];
    int t = threadIdx.x;
    if (MODE == 0) {
        wsh[t] = Wn[t & 255];  // 256 weights, 256 threads
    }
    if (MODE == 2) {
        for (int i = t; i < 640; i += 256) wsh[i] = Wn[i];
        if (t < 40) bsh[t] = postBias[t];
    }
    __syncthreads();

    const __half* inF = inA ? g_hA : g_hB;
    __half* outF = inA ? g_hB : g_hA;

    int node = g_order[blockIdx.x * 64 + (t >> 2)];  // degree-sorted order
    int sub = t & 3;
    float di = g_dis[node];
    float4 acc = agg_edge((const uint2*)inF, node, sub);
    acc.x *= di; acc.y *= di; acc.z *= di; acc.w *= di;  // out = dis_d * sum

    if (MODE != 2) {  // bias + relu
        float4 b4 = __ldg(&((const float4*)preBias)[sub]);
        acc.x = fmaxf(acc.x + b4.x, 0.f);
        acc.y = fmaxf(acc.y + b4.y, 0.f);
        acc.z = fmaxf(acc.z + b4.z, 0.f);
        acc.w = fmaxf(acc.w + b4.w, 0.f);
    }

    if (MODE == 1) {  // store dis * h for next layer's unweighted agg
        acc.x *= di; acc.y *= di; acc.z *= di; acc.w *= di;
        ((uint2*)outF)[node * 4 + sub] = f4_to_h4(acc);
        return;
    }

    // share the node's full 16-vector across its 4-lane group
    float* hr = &hsh[(t >> 2) * 17];
    hr[sub * 4 + 0] = acc.x;
    hr[sub * 4 + 1] = acc.y;
    hr[sub * 4 + 2] = acc.z;
    hr[sub * 4 + 3] = acc.w;
    __syncwarp();

    if (MODE == 0) {  // 16x16 transform, store pre-scaled by dis
        float o[4];
#pragma unroll
        for (int j = 0; j < 4; j++) {
            int col = sub * 4 + j;
            float s = 0.f;
#pragma unroll
            for (int k = 0; k < 16; k++) s = fmaf(hr[k], wsh[k * 16 + col], s);
            o[j] = s * di;
        }
        ((uint2*)outF)[node * 4 + sub] = f4_to_h4(make_float4(o[0], o[1], o[2], o[3]));
    } else {  // MODE 2: 16x40 output transform + log_softmax
        float o[10];
#pragma unroll
        for (int j = 0; j < 10; j++) {
            int col = sub * 10 + j;
            float s = bsh[col];
#pragma unroll
            for (int k = 0; k < 16; k++) s = fmaf(hr[k], wsh[k * 40 + col], s);
            o[j] = s;
        }
        float m = o[0];
#pragma unroll
        for (int j = 1; j < 10; j++) m = fmaxf(m, o[j]);
        m = fmaxf(m, __shfl_xor_sync(0xffffffffu, m, 1));
        m = fmaxf(m, __shfl_xor_sync(0xffffffffu, m, 2));
        float se = 0.f;
#pragma unroll
        for (int j = 0; j < 10; j++) se += __expf(o[j] - m);
        se += __shfl_xor_sync(0xffffffffu, se, 1);
        se += __shfl_xor_sync(0xffffffffu, se, 2);
        float l = m + __logf(se);
#pragma unroll
        for (int j = 0; j < 10; j++)
            fout[(size_t)node * 40 + sub * 10 + j] = o[j] - l;
    }
}

// ---------------- launch ----------------
extern "C" void kernel_launch(void* const* d_in, const int* in_sizes, int n_in,
                              void* d_out, int out_size) {
    const float* x     = (const float*)d_in[0];
    const float* w_in  = (const float*)d_in[1];
    const float* b_in  = (const float*)d_in[2];
    const float* w_hid = (const float*)d_in[3];
    const float* b_hid = (const float*)d_in[4];
    const float* w_out = (const float*)d_in[5];
    const float* b_out = (const float*)d_in[6];
    const int*   ei    = (const int*)d_in[7];   // JAX x64 disabled -> int32
    float* out = (float*)d_out;

    const int NB_N = (NN + 255) / 256;   // 782
    const int NB_E = EE / 256;           // 25000
    const int NB_S = (NN + 1023) / 1024; // 196
    const int NB_A = NN / 64;            // 3125 (exact)

    // CSR build
    k_zero<<<NB_N, 256>>>();
    k_hist<<<NB_E, 256>>>(ei);
    k_scan1<<<NB_S, 1024>>>();
    k_scan2<<<1, 32>>>(NB_S);
    k_scan3<<<NB_N, 256>>>();
    k_scatter<<<NB_E, 256>>>(ei);

    // degree counting sort
    k_dhist<<<NB_N, 256>>>();
    k_dscan<<<1, NBIN>>>();
    k_dplace<<<NB_N, 256>>>();

    // t0-hat = dis * (x @ w_in)  -> g_hA
    k_xw<<<NN / 16, 256>>>(x, w_in);

    // layers 1..8: fused agg + bias + relu + next 16x16 transform (ping-pong)
    k_agg<0><<<NB_A, 256>>>(1, b_in,         w_hid + 0 * 256, nullptr, nullptr);
    k_agg<0><<<NB_A, 256>>>(0, b_hid + 0*16, w_hid + 1 * 256, nullptr, nullptr);
    k_agg<0><<<NB_A, 256>>>(1, b_hid + 1*16, w_hid + 2 * 256, nullptr, nullptr);
    k_agg<0><<<NB_A, 256>>>(0, b_hid + 2*16, w_hid + 3 * 256, nullptr, nullptr);
    k_agg<0><<<NB_A, 256>>>(1, b_hid + 3*16, w_hid + 4 * 256, nullptr, nullptr);
    k_agg<0><<<NB_A, 256>>>(0, b_hid + 4*16, w_hid + 5 * 256, nullptr, nullptr);
    k_agg<0><<<NB_A, 256>>>(1, b_hid + 5*16, w_hid + 6 * 256, nullptr, nullptr);
    k_agg<0><<<NB_A, 256>>>(0, b_hid + 6*16, w_hid + 7 * 256, nullptr, nullptr);
    // layer 9: h9-hat = dis*relu(dis*agg(t8) + b_hid[7])   (hA -> hB)
    k_agg<1><<<NB_A, 256>>>(1, b_hid + 7*16, nullptr, nullptr, nullptr);
    // layer 10: out = log_softmax((dis*agg(h9-hat)) @ w_out + b_out)
    k_agg<2><<<NB_A, 256>>>(0, nullptr, w_out, b_out, out);
}

// round 6
// speedup vs baseline: 1.2373x; 1.0365x over previous
#include <cuda_runtime.h>
#include <cuda_fp16.h>

#define NN 200000
#define EE 6400000
#define HH 16
#define CC 40
#define NBIN 512
#define NG (NN / 8)            // 25000 warp-groups of 8 nodes
#define NGB ((NG + 1023) / 1024) // 25
#define EIL_CAP 7000000        // interleaved edge slots (sorted => ~6.45M used)

// ---------------- scratch (static device globals; no allocation) ----------------
__device__ int       g_cnt[NN];
__device__ int       g_scan[NN];
__device__ int       g_rowptr[NN + 1];
__device__ int       g_cursor[NN];
__device__ int       g_bsum[256];
__device__ int       g_boff[256];
__device__ float     g_dis[NN];
__device__ int       g_srcs[EE];      // CSR src indices (intermediate)
__device__ int       g_order[NN];     // degree-sorted node order
__device__ int       g_dbin[NBIN];
__device__ int       g_doff[NBIN];
__device__ int       g_dcur[NBIN];
// warp-interleaved ELL edge list
__device__ int       g_eil[EIL_CAP];
__device__ int       g_gmax[NG];      // per-group max degree
__device__ int       g_gscan[NG];
__device__ int       g_gbsum[NGB];
__device__ int       g_gboff[NGB];
__device__ int       g_gbase[NG + 1]; // slot base per group (units of ints)
// features fp16, PRE-SCALED by dis[node]; row NN is an always-zero pad row
__device__ __half    g_hA[(NN + 1) * HH];
__device__ __half    g_hB[(NN + 1) * HH];

// ---------------- CSR construction ----------------
__global__ void k_zero() {
    int i = blockIdx.x * 256 + threadIdx.x;
    if (i < NN) g_cnt[i] = 0;
    if (i < NBIN) { g_dbin[i] = 0; g_dcur[i] = 0; }
    if (i < 4) ((uint2*)g_hA)[NN * 4 + i] = make_uint2(0u, 0u);   // zero pad row
    else if (i < 8) ((uint2*)g_hB)[NN * 4 + (i - 4)] = make_uint2(0u, 0u);
}

__global__ void k_hist(const int* __restrict__ ei) {
    int e = blockIdx.x * 256 + threadIdx.x;
    if (e < EE) atomicAdd(&g_cnt[ei[EE + e]], 1);
}

__global__ void k_scan1() {  // 1024 elems per block, inclusive scan
    __shared__ int sh[1024];
    int t = threadIdx.x;
    int i = blockIdx.x * 1024 + t;
    int v = (i < NN) ? g_cnt[i] : 0;
    sh[t] = v;
    for (int off = 1; off < 1024; off <<= 1) {
        __syncthreads();
        int u = (t >= off) ? sh[t - off] : 0;
        __syncthreads();
        sh[t] += u;
    }
    __syncthreads();
    if (i < NN) g_scan[i] = sh[t];
    if (t == 1023) g_bsum[blockIdx.x] = sh[1023];
}

__global__ void k_scan2(int nb) {  // parallel scan of block sums (nb <= 256)
    __shared__ int sh[256];
    int t = threadIdx.x;
    sh[t] = (t < nb) ? g_bsum[t] : 0;
    for (int off = 1; off < 256; off <<= 1) {
        __syncthreads();
        int u = (t >= off) ? sh[t - off] : 0;
        __syncthreads();
        sh[t] += u;
    }
    __syncthreads();
    if (t < nb) g_boff[t] = sh[t] - g_bsum[t];  // exclusive
}

__global__ void k_scan3() {  // rowptr/cursor + dis (fused)
    int i = blockIdx.x * 256 + threadIdx.x;
    if (i < NN) {
        int ex = g_boff[i >> 10] + g_scan[i] - g_cnt[i];  // exclusive prefix
        g_rowptr[i] = ex;
        g_cursor[i] = ex;
        g_dis[i] = rsqrtf((float)(g_cnt[i] + 1));  // +1 self loop
    }
    if (i == 0) g_rowptr[NN] = EE;
}

__global__ void k_scatter(const int* __restrict__ ei) {
    int e = blockIdx.x * 256 + threadIdx.x;
    if (e < EE) {
        int s = ei[e];
        int d = ei[EE + e];
        int p = atomicAdd(&g_cursor[d], 1);
        g_srcs[p] = s;
    }
}

// ---------------- degree counting sort ----------------
__global__ void k_dhist() {
    int i = blockIdx.x * 256 + threadIdx.x;
    if (i < NN) {
        int d = g_cnt[i]; if (d > NBIN - 1) d = NBIN - 1;
        atomicAdd(&g_dbin[d], 1);
    }
}

__global__ void k_dscan() {
    __shared__ int sh[NBIN];
    int t = threadIdx.x;
    sh[t] = g_dbin[t];
    for (int off = 1; off < NBIN; off <<= 1) {
        __syncthreads();
        int u = (t >= off) ? sh[t - off] : 0;
        __syncthreads();
        sh[t] += u;
    }
    __syncthreads();
    g_doff[t] = sh[t] - g_dbin[t];
}

__global__ void k_dplace() {
    int i = blockIdx.x * 256 + threadIdx.x;
    if (i < NN) {
        int d = g_cnt[i]; if (d > NBIN - 1) d = NBIN - 1;
        int p = g_doff[d] + atomicAdd(&g_dcur[d], 1);
        g_order[p] = i;
    }
}

// ---------------- warp-interleaved ELL build ----------------
__global__ void k_gmax() {  // per-group max degree
    int g = blockIdx.x * 256 + threadIdx.x;
    if (g < NG) {
        int m = 0;
#pragma unroll
        for (int j = 0; j < 8; j++) {
            int d = g_cnt[g_order[g * 8 + j]];
            m = d > m ? d : m;
        }
        g_gmax[g] = m;
    }
}

__global__ void k_gscan1() {
    __shared__ int sh[1024];
    int t = threadIdx.x;
    int i = blockIdx.x * 1024 + t;
    int v = (i < NG) ? g_gmax[i] : 0;
    sh[t] = v;
    for (int off = 1; off < 1024; off <<= 1) {
        __syncthreads();
        int u = (t >= off) ? sh[t - off] : 0;
        __syncthreads();
        sh[t] += u;
    }
    __syncthreads();
    if (i < NG) g_gscan[i] = sh[t];
    if (t == 1023) g_gbsum[blockIdx.x] = sh[1023];
}

__global__ void k_gscan2() {  // NGB=25 sums, one warp
    if (threadIdx.x == 0) {
        int run = 0;
        for (int j = 0; j < NGB; j++) { g_gboff[j] = run; run += g_gbsum[j]; }
    }
}

__global__ void k_gscan3() {
    int g = blockIdx.x * 256 + threadIdx.x;
    if (g < NG) {
        int ex = g_gboff[g >> 10] + g_gscan[g] - g_gmax[g];
        g_gbase[g] = ex * 8;
    }
    if (g == 0) g_gbase[NG] = (g_gboff[NGB - 1] + g_gbsum[NGB - 1]) * 8;
}

__global__ void k_fill() {  // one block per group: interleave + pad with NN
    int g = blockIdx.x;
    int t = threadIdx.x;
    int base = g_gbase[g];
    int maxd = (g_gbase[g + 1] - base) >> 3;
    int j = t & 7;
    int node = g_order[g * 8 + j];
    int r = g_rowptr[node];
    int d = g_rowptr[node + 1] - r;
    for (int i = t >> 3; i < maxd; i += 32)
        g_eil[base + i * 8 + j] = (i < d) ? g_srcs[r + i] : NN;
}

// -------- first transform: store dis * (x @ w_in)  (200000x128 @ 128x16) --------
__global__ __launch_bounds__(256) void k_xw(const float* __restrict__ x,
                                            const float* __restrict__ w) {
    __shared__ float xs[16 * 128];
    __shared__ float ws[128 * 16];
    int t = threadIdx.x;
    for (int i = t; i < 2048; i += 256) ws[i] = w[i];
    const float* xb = x + (size_t)blockIdx.x * 2048;
    for (int i = t; i < 2048; i += 256) xs[i] = xb[i];
    __syncthreads();
    int ry = t >> 4, c = t & 15;
    float s = 0.f;
#pragma unroll
    for (int k = 0; k < 128; k++) s = fmaf(xs[ry * 128 + k], ws[k * 16 + c], s);
    int node = blockIdx.x * 16 + ry;
    g_hA[(size_t)node * 16 + c] = __float2half_rn(s * g_dis[node]);
}

// ---------------- fused aggregation layers ----------------
__device__ __forceinline__ float4 h4_to_f4(uint2 hv) {
    float2 lo = __half22float2(*(__half2*)&hv.x);
    float2 hi = __half22float2(*(__half2*)&hv.y);
    return make_float4(lo.x, lo.y, hi.x, hi.y);
}

__device__ __forceinline__ uint2 f4_to_h4(float4 v) {
    __half2 lo = __floats2half2_rn(v.x, v.y);
    __half2 hi = __floats2half2_rn(v.z, v.w);
    uint2 r; r.x = *(unsigned int*)&lo; r.y = *(unsigned int*)&hi;
    return r;
}

// MODE 0: h = relu(dis*agg+b); store dis*(h @ Wn)               [used 8x]
// MODE 1: store dis*relu(dis*agg+b)                              [produces h9-hat]
// MODE 2: o = (dis*agg) @ w_out + b_out; out = log_softmax(o)    [final]
template <int MODE>
__global__ __launch_bounds__(256) void k_agg(int inA,
                                             const float* __restrict__ preBias,
                                             const float* __restrict__ Wn,
                                             const float* __restrict__ postBias,
                                             float* __restrict__ fout) {
    __shared__ float wsh[640];
    __shared__ float bsh[40];
    __shared__ float hsh[64 * 17];
    int t = threadIdx.x;
    if (MODE == 0) {
        wsh[t] = Wn[t & 255];
    }
    if (MODE == 2) {
        for (int i = t; i < 640; i += 256) wsh[i] = Wn[i];
        if (t < 40) bsh[t] = postBias[t];
    }
    __syncthreads();

    const __half* inF = inA ? g_hA : g_hB;
    __half* outF = inA ? g_hB : g_hA;
    const uint2* in4 = (const uint2*)inF;

    int gw = blockIdx.x * 8 + (t >> 5);   // group id == global warp id
    int lane = t & 31;
    int j = lane >> 2;                     // node slot within group
    int sub = lane & 3;
    int node = g_order[gw * 8 + j];
    float di = g_dis[node];

    // unweighted aggregation over warp-interleaved edge list
    float4 acc = h4_to_f4(__ldg(&in4[node * 4 + sub]));  // self loop
    int base = g_gbase[gw];
    int maxd = (g_gbase[gw + 1] - base) >> 3;
    const int* ep = g_eil + base + j;
#pragma unroll 4
    for (int i = 0; i < maxd; i++) {
        int s = __ldg(ep + i * 8);         // 32B coalesced per warp
        float4 v = h4_to_f4(__ldg(&in4[s * 4 + sub]));
        acc.x += v.x; acc.y += v.y; acc.z += v.z; acc.w += v.w;
    }
    acc.x *= di; acc.y *= di; acc.z *= di; acc.w *= di;

    if (MODE != 2) {  // bias + relu
        float4 b4 = __ldg(&((const float4*)preBias)[sub]);
        acc.x = fmaxf(acc.x + b4.x, 0.f);
        acc.y = fmaxf(acc.y + b4.y, 0.f);
        acc.z = fmaxf(acc.z + b4.z, 0.f);
        acc.w = fmaxf(acc.w + b4.w, 0.f);
    }

    if (MODE == 1) {  // store dis*h for next layer
        acc.x *= di; acc.y *= di; acc.z *= di; acc.w *= di;
        ((uint2*)outF)[node * 4 + sub] = f4_to_h4(acc);
        return;
    }

    float* hr = &hsh[(t >> 2) * 17];
    hr[sub * 4 + 0] = acc.x;
    hr[sub * 4 + 1] = acc.y;
    hr[sub * 4 + 2] = acc.z;
    hr[sub * 4 + 3] = acc.w;
    __syncwarp();

    if (MODE == 0) {  // 16x16 transform, store pre-scaled by dis
        float o[4];
#pragma unroll
        for (int jj = 0; jj < 4; jj++) {
            int col = sub * 4 + jj;
            float s = 0.f;
#pragma unroll
            for (int k = 0; k < 16; k++) s = fmaf(hr[k], wsh[k * 16 + col], s);
            o[jj] = s * di;
        }
        ((uint2*)outF)[node * 4 + sub] = f4_to_h4(make_float4(o[0], o[1], o[2], o[3]));
    } else {  // MODE 2: 16x40 output transform + log_softmax
        float o[10];
#pragma unroll
        for (int jj = 0; jj < 10; jj++) {
            int col = sub * 10 + jj;
            float s = bsh[col];
#pragma unroll
            for (int k = 0; k < 16; k++) s = fmaf(hr[k], wsh[k * 40 + col], s);
            o[jj] = s;
        }
        float m = o[0];
#pragma unroll
        for (int jj = 1; jj < 10; jj++) m = fmaxf(m, o[jj]);
        m = fmaxf(m, __shfl_xor_sync(0xffffffffu, m, 1));
        m = fmaxf(m, __shfl_xor_sync(0xffffffffu, m, 2));
        float se = 0.f;
#pragma unroll
        for (int jj = 0; jj < 10; jj++) se += __expf(o[jj] - m);
        se += __shfl_xor_sync(0xffffffffu, se, 1);
        se += __shfl_xor_sync(0xffffffffu, se, 2);
        float l = m + __logf(se);
#pragma unroll
        for (int jj = 0; jj < 10; jj++)
            fout[(size_t)node * 40 + sub * 10 + jj] = o[jj] - l;
    }
}

// ---------------- launch ----------------
extern "C" void kernel_launch(void* const* d_in, const int* in_sizes, int n_in,
                              void* d_out, int out_size) {
    const float* x     = (const float*)d_in[0];
    const float* w_in  = (const float*)d_in[1];
    const float* b_in  = (const float*)d_in[2];
    const float* w_hid = (const float*)d_in[3];
    const float* b_hid = (const float*)d_in[4];
    const float* w_out = (const float*)d_in[5];
    const float* b_out = (const float*)d_in[6];
    const int*   ei    = (const int*)d_in[7];   // JAX x64 disabled -> int32
    float* out = (float*)d_out;

    const int NB_N = (NN + 255) / 256;   // 782
    const int NB_E = EE / 256;           // 25000
    const int NB_S = (NN + 1023) / 1024; // 196
    const int NB_A = NN / 64;            // 3125
    const int NB_G = (NG + 255) / 256;   // 98

    // CSR build
    k_zero<<<NB_N, 256>>>();
    k_hist<<<NB_E, 256>>>(ei);
    k_scan1<<<NB_S, 1024>>>();
    k_scan2<<<1, 256>>>(NB_S);
    k_scan3<<<NB_N, 256>>>();
    k_scatter<<<NB_E, 256>>>(ei);

    // degree counting sort
    k_dhist<<<NB_N, 256>>>();
    k_dscan<<<1, NBIN>>>();
    k_dplace<<<NB_N, 256>>>();

    // warp-interleaved ELL
    k_gmax<<<NB_G, 256>>>();
    k_gscan1<<<NGB, 1024>>>();
    k_gscan2<<<1, 32>>>();
    k_gscan3<<<NB_G, 256>>>();
    k_fill<<<NG, 256>>>();

    // t0-hat = dis * (x @ w_in)  -> g_hA
    k_xw<<<NN / 16, 256>>>(x, w_in);

    // layers 1..8: fused agg + bias + relu + next 16x16 transform (ping-pong)
    k_agg<0><<<NB_A, 256>>>(1, b_in,         w_hid + 0 * 256, nullptr, nullptr);
    k_agg<0><<<NB_A, 256>>>(0, b_hid + 0*16, w_hid + 1 * 256, nullptr, nullptr);
    k_agg<0><<<NB_A, 256>>>(1, b_hid + 1*16, w_hid + 2 * 256, nullptr, nullptr);
    k_agg<0><<<NB_A, 256>>>(0, b_hid + 2*16, w_hid + 3 * 256, nullptr, nullptr);
    k_agg<0><<<NB_A, 256>>>(1, b_hid + 3*16, w_hid + 4 * 256, nullptr, nullptr);
    k_agg<0><<<NB_A, 256>>>(0, b_hid + 4*16, w_hid + 5 * 256, nullptr, nullptr);
    k_agg<0><<<NB_A, 256>>>(1, b_hid + 5*16, w_hid + 6 * 256, nullptr, nullptr);
    k_agg<0><<<NB_A, 256>>>(0, b_hid + 6*16, w_hid + 7 * 256, nullptr, nullptr);
    // layer 9: h9-hat = dis*relu(dis*agg(t8) + b_hid[7])   (hA -> hB)
    k_agg<1><<<NB_A, 256>>>(1, b_hid + 7*16, nullptr, nullptr, nullptr);
    // layer 10: out = log_softmax((dis*agg(h9-hat)) @ w_out + b_out)
    k_agg<2><<<NB_A, 256>>>(0, nullptr, w_out, b_out, out);
}